// round 12
// baseline (speedup 1.0000x reference)
#include <cuda_runtime.h>
#include <cuda_fp16.h>
#include <math.h>

#define MAX_NE 100000
#define MAX_NR 1000
#define MAX_E  1000000
#define PACK_CAP 1800064   // E + padding + guard

// ---------------- scratch ----------------
__device__ float  g_sh[MAX_NE];
__device__ float  g_st[MAX_NE];
__device__ float  g_sr[MAX_NR];
// fp16 P tables: [side(2)][rel][256]; 512B per row, L2-resident (1 MB total)
__device__ __half g_P16[2 * MAX_NR * 256];
__device__ int    g_cnt_h[MAX_NE];
__device__ int    g_cnt_t[MAX_NE];
__device__ int    g_starts_h[MAX_NE + 1];  // PADDED exclusive starts (multiples of 4 edges)
__device__ int    g_starts_t[MAX_NE + 1];
__device__ int    g_cur_h[MAX_NE];
__device__ int    g_cur_t[MAX_NE];
// pad slots are NEVER written: BSS-zero => {z=0, off=0} -> loads P row 0, FFMA x0 = inert.
__device__ float2 g_pack_h[PACK_CAP];
__device__ float2 g_pack_t[PACK_CAP];
__device__ int    g_bsum[2][160];

// ---------------- fused attention scores + per-node scratch zeroing ----------------
__global__ void k_scores(const float4* __restrict__ xe, const float4* __restrict__ xr,
                         const float4* __restrict__ wah4, const float4* __restrict__ wat4,
                         const float4* __restrict__ war4, int n_e, int n_r) {
    int gw = (blockIdx.x * blockDim.x + threadIdx.x) >> 5;
    int lane = threadIdx.x & 31;
    if (gw < n_e) {
        float4 v = xe[(size_t)gw * 32 + lane];
        float4 a = wah4[lane];
        float4 b = wat4[lane];
        float da = v.x * a.x + v.y * a.y + v.z * a.z + v.w * a.w;
        float db = v.x * b.x + v.y * b.y + v.z * b.z + v.w * b.w;
#pragma unroll
        for (int o = 16; o > 0; o >>= 1) {
            da += __shfl_xor_sync(0xffffffffu, da, o);
            db += __shfl_xor_sync(0xffffffffu, db, o);
        }
        if (lane == 0) { g_sh[gw] = da; g_st[gw] = db; }
        else if (lane == 1) g_cnt_h[gw] = 0;
        else if (lane == 2) g_cnt_t[gw] = 0;
    } else if (gw < n_e + n_r) {
        int r = gw - n_e;
        float4 v = xr[r * 32 + lane];
        float4 a = war4[lane];
        float d = v.x * a.x + v.y * a.y + v.z * a.z + v.w * a.w;
#pragma unroll
        for (int o = 16; o > 0; o >>= 1) d += __shfl_xor_sync(0xffffffffu, d, o);
        if (lane == 0) g_sr[r] = d;
    }
}

// ---------------- fused relation pipeline: x_r -> hid -> msg -> P (fp16, row-major) -----
#define RPB 8
__global__ __launch_bounds__(256) void k_rgemm(const float* __restrict__ xr,
                                               const float* __restrict__ W1, const float* __restrict__ b1,
                                               const float* __restrict__ W2, const float* __restrict__ b2,
                                               const float* __restrict__ Wr, int n_r) {
    __shared__ float sx[RPB * 128];
    __shared__ float shid[RPB * 256];
    __shared__ float smsg[RPB * 128];
    __shared__ float wt[32 * 256];
    int r0 = blockIdx.x * RPB;
    int tid = threadIdx.x;

    for (int i = tid; i < RPB * 128; i += 256) {
        int rr = i >> 7, k = i & 127, r = r0 + rr;
        sx[i] = (r < n_r) ? xr[r * 128 + k] : 0.f;
    }

    // ---- hid = x @ W1 + b1 ----
    {
        int j = tid;
        float acc[RPB];
        float bj = b1[j];
#pragma unroll
        for (int u = 0; u < RPB; u++) acc[u] = bj;
        for (int k0 = 0; k0 < 128; k0 += 32) {
            __syncthreads();
            for (int i = tid; i < 8192; i += 256)
                wt[i] = W1[(k0 + (i >> 8)) * 256 + (i & 255)];
            __syncthreads();
#pragma unroll 8
            for (int kk = 0; kk < 32; kk++) {
                float w = wt[kk * 256 + j];
#pragma unroll
                for (int u = 0; u < RPB; u++) acc[u] += sx[u * 128 + k0 + kk] * w;
            }
        }
#pragma unroll
        for (int u = 0; u < RPB; u++) shid[u * 256 + j] = acc[u];
    }
    __syncthreads();

    // ---- msg = x + hid @ W2 + b2 ----
    {
        int j = tid & 127, half = tid >> 7;
        float acc[RPB];
#pragma unroll
        for (int u = 0; u < RPB; u++) acc[u] = 0.f;
        for (int t = 0; t < 4; t++) {
            __syncthreads();
            for (int i = tid; i < 8192; i += 256) {
                int hh = i >> 12, loc = i & 4095, row = loc >> 7, col = loc & 127;
                wt[i] = W2[(hh * 128 + t * 32 + row) * 128 + col];
            }
            __syncthreads();
            const float* w = wt + half * 4096;
            int kbase = half * 128 + t * 32;
#pragma unroll 8
            for (int kk = 0; kk < 32; kk++) {
                float wv = w[kk * 128 + j];
#pragma unroll
                for (int u = 0; u < RPB; u++) acc[u] += shid[u * 256 + kbase + kk] * wv;
            }
        }
        __syncthreads();
        float* red = wt;
#pragma unroll
        for (int u = 0; u < RPB; u++) red[u * 256 + half * 128 + j] = acc[u];
        __syncthreads();
        if (half == 0) {
            float bj = b2[j];
#pragma unroll
            for (int u = 0; u < RPB; u++)
                smsg[u * 128 + j] = sx[u * 128 + j] + bj + red[u * 256 + j] + red[u * 256 + 128 + j];
        }
    }
    __syncthreads();

    // ---- P_side[r][j] = (msg @ Wr_side)[r][j], fp16 row-major ----
    {
        int j = tid;
        for (int side = 0; side < 2; side++) {
            float acc[RPB];
#pragma unroll
            for (int u = 0; u < RPB; u++) acc[u] = 0.f;
            for (int k0 = 0; k0 < 128; k0 += 32) {
                __syncthreads();
                for (int i = tid; i < 8192; i += 256)
                    wt[i] = Wr[(side * 128 + k0 + (i >> 8)) * 256 + (i & 255)];
                __syncthreads();
#pragma unroll 8
                for (int kk = 0; kk < 32; kk++) {
                    float w = wt[kk * 256 + j];
#pragma unroll
                    for (int u = 0; u < RPB; u++) acc[u] += smsg[u * 128 + k0 + kk] * w;
                }
            }
#pragma unroll
            for (int u = 0; u < RPB; u++) {
                int r = r0 + u;
                if (r < n_r) g_P16[((size_t)side * n_r + r) * 256 + j] = __float2half_rn(acc[u]);
            }
        }
    }
}

// ---------------- histogram (int4 vectorized, 4 edges/thread) ----------------
__global__ void k_hist(const int* __restrict__ h, const int* __restrict__ t, int E) {
    int i = blockIdx.x * blockDim.x + threadIdx.x;
    int e = i * 4;
    if (e + 3 < E) {
        int4 hv = *(const int4*)(h + e);
        int4 tv = *(const int4*)(t + e);
        atomicAdd(&g_cnt_h[hv.x], 1); atomicAdd(&g_cnt_h[hv.y], 1);
        atomicAdd(&g_cnt_h[hv.z], 1); atomicAdd(&g_cnt_h[hv.w], 1);
        atomicAdd(&g_cnt_t[tv.x], 1); atomicAdd(&g_cnt_t[tv.y], 1);
        atomicAdd(&g_cnt_t[tv.z], 1); atomicAdd(&g_cnt_t[tv.w], 1);
    } else {
        for (int k = e; k < E; k++) {
            atomicAdd(&g_cnt_h[h[k]], 1);
            atomicAdd(&g_cnt_t[t[k]], 1);
        }
    }
}

// ---------------- scan over PADDED counts (pad to multiple of 4 edges) ----------------
__global__ void k_scan1(int n_e) {
    __shared__ int s[1024];
    int y = blockIdx.y;
    const int* cnt = y ? g_cnt_t : g_cnt_h;
    int* st = y ? g_starts_t : g_starts_h;
    int i = blockIdx.x * 1024 + threadIdx.x;
    int v = (i < n_e) ? ((cnt[i] + 3) & ~3) : 0;
    s[threadIdx.x] = v;
    __syncthreads();
    for (int o = 1; o < 1024; o <<= 1) {
        int tv = (threadIdx.x >= (unsigned)o) ? s[threadIdx.x - o] : 0;
        __syncthreads();
        s[threadIdx.x] += tv;
        __syncthreads();
    }
    if (i < n_e) st[i] = s[threadIdx.x];
    if (threadIdx.x == 1023) g_bsum[y][blockIdx.x] = s[1023];
}

// parallel scan of block sums (nb <= 128)
__global__ void k_scan2(int nb) {
    __shared__ int s[128];
    int y = blockIdx.x;
    int tid = threadIdx.x;
    int v = (tid < nb) ? g_bsum[y][tid] : 0;
    s[tid] = v;
    __syncthreads();
    for (int o = 1; o < 128; o <<= 1) {
        int t = (tid >= o) ? s[tid - o] : 0;
        __syncthreads();
        s[tid] += t;
        __syncthreads();
    }
    if (tid < nb) g_bsum[y][tid] = s[tid] - v;   // exclusive
    if (tid == nb - 1) g_bsum[y][nb] = s[tid];   // total
}

__global__ void k_scan3(int n_e, int nb) {
    int y = blockIdx.y;
    const int* cnt = y ? g_cnt_t : g_cnt_h;
    int* st = y ? g_starts_t : g_starts_h;
    int* cur = y ? g_cur_t : g_cur_h;
    int i = blockIdx.x * 1024 + threadIdx.x;
    if (i < n_e) {
        int pc = (cnt[i] + 3) & ~3;
        int ex = st[i] - pc + g_bsum[y][blockIdx.x];
        st[i] = ex;
        cur[i] = ex;
    }
    if (i == 0) st[n_e] = g_bsum[y][nb];
}

// ---------------- place edges (off = BYTE offset r*512), 2 edges/thread ----------------
__global__ void k_place(const int* __restrict__ h, const int* __restrict__ t,
                        const int* __restrict__ rel, int E) {
    int i = blockIdx.x * blockDim.x + threadIdx.x;
    int e = i * 2;
    if (e >= E) return;
    int ne = min(2, E - e);
#pragma unroll
    for (int u = 0; u < 2; u++) {
        if (u < ne) {
            int hn = h[e + u], tn = t[e + u], r = rel[e + u];
            float sr = g_sr[r];
            float lh = g_sh[hn] + sr; lh = (lh > 0.f) ? lh : 0.01f * lh;
            float lt = g_st[tn] + sr; lt = (lt > 0.f) ? lt : 0.01f * lt;
            float zh = __expf(lh), zt = __expf(lt);
            float ro = __int_as_float(r * 512);
            int ph = atomicAdd(&g_cur_h[hn], 1);
            g_pack_h[ph] = make_float2(zh, ro);
            int pt = atomicAdd(&g_cur_t[tn], 1);
            g_pack_t[pt] = make_float2(zt, ro);
        }
    }
}

// ---------------- main SpMM: SINGLE PASS, h+t sides FUSED (2x loads in flight) ----------
// Warp per node; per edge one coalesced LDG.128/lane fetches the full 512B P row.
// h and t edge loops iterate concurrently: 8 pack + 8 row loads in flight per iter.
__global__ __launch_bounds__(256) void k_main(const float* __restrict__ br,
                                              float* __restrict__ out,
                                              int n_e, int n_r) {
    int gw = (blockIdx.x * blockDim.x + threadIdx.x) >> 5;
    int lane = threadIdx.x & 31;
    if (gw >= n_e) return;
    int n = gw;

    const char* Pb = (const char*)g_P16 + lane * 16;   // this lane's 16B of each row
    const char* Pt = Pb + (size_t)n_r * 512;

    int h0 = g_starts_h[n], h1 = g_starts_h[n + 1];
    int t0 = g_starts_t[n], t1 = g_starts_t[n + 1];

    float zsh = 0.f, zst = 0.f;
    float ah[8], at[8];
#pragma unroll
    for (int k = 0; k < 8; k++) { ah[k] = 0.f; at[k] = 0.f; }

    const float2* __restrict__ pkh = g_pack_h;
    const float2* __restrict__ pkt = g_pack_t;
    int lenh = h1 - h0, lent = t1 - t0;
    int m = max(lenh, lent);
    for (int off = 0; off < m; off += 4) {
#pragma unroll
        for (int u = 0; u < 4; u++) {
            int jh = h0 + off + u;
            int jt = t0 + off + u;
            float2 ph = (jh < h1) ? pkh[jh] : make_float2(0.f, 0.f);
            float2 pt = (jt < t1) ? pkt[jt] : make_float2(0.f, 0.f);
            uint4 rh = *(const uint4*)(Pb + __float_as_int(ph.y));
            uint4 rt = *(const uint4*)(Pt + __float_as_int(pt.y));
            zsh += ph.x;
            zst += pt.x;
            {
                float2 v0 = __half22float2(*(const __half2*)&rh.x);
                float2 v1 = __half22float2(*(const __half2*)&rh.y);
                float2 v2 = __half22float2(*(const __half2*)&rh.z);
                float2 v3 = __half22float2(*(const __half2*)&rh.w);
                ah[0] = fmaf(ph.x, v0.x, ah[0]); ah[1] = fmaf(ph.x, v0.y, ah[1]);
                ah[2] = fmaf(ph.x, v1.x, ah[2]); ah[3] = fmaf(ph.x, v1.y, ah[3]);
                ah[4] = fmaf(ph.x, v2.x, ah[4]); ah[5] = fmaf(ph.x, v2.y, ah[5]);
                ah[6] = fmaf(ph.x, v3.x, ah[6]); ah[7] = fmaf(ph.x, v3.y, ah[7]);
            }
            {
                float2 v0 = __half22float2(*(const __half2*)&rt.x);
                float2 v1 = __half22float2(*(const __half2*)&rt.y);
                float2 v2 = __half22float2(*(const __half2*)&rt.z);
                float2 v3 = __half22float2(*(const __half2*)&rt.w);
                at[0] = fmaf(pt.x, v0.x, at[0]); at[1] = fmaf(pt.x, v0.y, at[1]);
                at[2] = fmaf(pt.x, v1.x, at[2]); at[3] = fmaf(pt.x, v1.y, at[3]);
                at[4] = fmaf(pt.x, v2.x, at[4]); at[5] = fmaf(pt.x, v2.y, at[5]);
                at[6] = fmaf(pt.x, v3.x, at[6]); at[7] = fmaf(pt.x, v3.y, at[7]);
            }
        }
    }

    float invh = 1.f / (zsh + 1e-16f);
    float invt = 1.f / (zst + 1e-16f);

    float res[8];
    {
        float4 b0 = *(const float4*)(br + lane * 8);
        float4 b1 = *(const float4*)(br + lane * 8 + 4);
        res[0] = b0.x; res[1] = b0.y; res[2] = b0.z; res[3] = b0.w;
        res[4] = b1.x; res[5] = b1.y; res[6] = b1.z; res[7] = b1.w;
    }
#pragma unroll
    for (int k = 0; k < 8; k++) res[k] = fmaf(at[k], invt, fmaf(ah[k], invh, res[k]));

    // ---- single coalesced store: 1 KB per warp ----
    float* o = out + (size_t)n * 256 + lane * 8;
    *(float4*)o = make_float4(res[0], res[1], res[2], res[3]);
    *(float4*)(o + 4) = make_float4(res[4], res[5], res[6], res[7]);
}

// ---------------- launch ----------------
extern "C" void kernel_launch(void* const* d_in, const int* in_sizes, int n_in,
                              void* d_out, int out_size) {
    const float* xe  = (const float*)d_in[0];
    const float* xr  = (const float*)d_in[1];
    const int*   ei  = (const int*)d_in[2];
    const int*   rel = (const int*)d_in[3];
    const float* wah = (const float*)d_in[5];
    const float* wat = (const float*)d_in[6];
    const float* war = (const float*)d_in[7];
    const float* W1  = (const float*)d_in[8];
    const float* b1  = (const float*)d_in[9];
    const float* W2  = (const float*)d_in[10];
    const float* b2  = (const float*)d_in[11];
    const float* Wr  = (const float*)d_in[12];
    const float* br  = (const float*)d_in[13];
    float* out = (float*)d_out;

    int n_e = in_sizes[0] / 128;
    int n_r = in_sizes[1] / 128;
    int E   = in_sizes[3];
    const int* h = ei;
    const int* t = ei + E;
    int nb = (n_e + 1023) / 1024;

    k_scores<<<((n_e + n_r) * 32 + 255) / 256, 256>>>((const float4*)xe, (const float4*)xr,
                                                      (const float4*)wah, (const float4*)wat,
                                                      (const float4*)war, n_e, n_r);
    k_rgemm<<<(n_r + RPB - 1) / RPB, 256>>>(xr, W1, b1, W2, b2, Wr, n_r);
    k_hist<<<(E / 4 + 256) / 256, 256>>>(h, t, E);
    k_scan1<<<dim3(nb, 2), 1024>>>(n_e);
    k_scan2<<<2, 128>>>(nb);
    k_scan3<<<dim3(nb, 2), 1024>>>(n_e, nb);
    k_place<<<(E / 2 + 256) / 256, 256>>>(h, t, rel, E);

    k_main<<<(n_e * 32 + 255) / 256, 256>>>(br, out, n_e, n_r);
}

// round 13
// speedup vs baseline: 1.1187x; 1.1187x over previous
#include <cuda_runtime.h>
#include <cuda_fp16.h>
#include <math.h>

#define MAX_NE 100000
#define MAX_NR 1000
#define MAX_E  1000000
#define PACK_CAP 1800064   // E + padding + guard

// ---------------- scratch ----------------
__device__ float  g_sh[MAX_NE];
__device__ float  g_st[MAX_NE];
__device__ float  g_sr[MAX_NR];
// fp16 P tables: [side(2)][rel][256]; 512B per row, L2-resident (1 MB total)
__device__ __half g_P16[2 * MAX_NR * 256];
__device__ int    g_cnt_h[MAX_NE];
__device__ int    g_cnt_t[MAX_NE];
__device__ int    g_starts_h[MAX_NE + 1];  // PADDED exclusive starts (multiples of 4 edges)
__device__ int    g_starts_t[MAX_NE + 1];
__device__ int    g_cur_h[MAX_NE];
__device__ int    g_cur_t[MAX_NE];
// pad slots are NEVER written: BSS-zero => {z=0, off=0} -> loads P row 0, FFMA x0 = inert.
__device__ float2 g_pack_h[PACK_CAP];
__device__ float2 g_pack_t[PACK_CAP];
__device__ int    g_bsum[2][160];

// P-row load: keep resident in L1 (hot 1MB table, re-read 2M times)
__device__ __forceinline__ uint4 ldg_row_resident(const void* p) {
    uint4 v;
    asm("ld.global.nc.L1::evict_last.v4.u32 {%0,%1,%2,%3}, [%4];"
        : "=r"(v.x), "=r"(v.y), "=r"(v.z), "=r"(v.w) : "l"(p));
    return v;
}
// pack load: streaming, read exactly once -> don't pollute L1
__device__ __forceinline__ float2 ldg_pack_stream(const float2* p) {
    float2 v;
    asm("ld.global.nc.L1::evict_first.v2.f32 {%0,%1}, [%2];"
        : "=f"(v.x), "=f"(v.y) : "l"(p));
    return v;
}

// ---------------- fused attention scores + per-node scratch zeroing ----------------
__global__ void k_scores(const float4* __restrict__ xe, const float4* __restrict__ xr,
                         const float4* __restrict__ wah4, const float4* __restrict__ wat4,
                         const float4* __restrict__ war4, int n_e, int n_r) {
    int gw = (blockIdx.x * blockDim.x + threadIdx.x) >> 5;
    int lane = threadIdx.x & 31;
    if (gw < n_e) {
        float4 v = xe[(size_t)gw * 32 + lane];
        float4 a = wah4[lane];
        float4 b = wat4[lane];
        float da = v.x * a.x + v.y * a.y + v.z * a.z + v.w * a.w;
        float db = v.x * b.x + v.y * b.y + v.z * b.z + v.w * b.w;
#pragma unroll
        for (int o = 16; o > 0; o >>= 1) {
            da += __shfl_xor_sync(0xffffffffu, da, o);
            db += __shfl_xor_sync(0xffffffffu, db, o);
        }
        if (lane == 0) { g_sh[gw] = da; g_st[gw] = db; }
        else if (lane == 1) g_cnt_h[gw] = 0;
        else if (lane == 2) g_cnt_t[gw] = 0;
    } else if (gw < n_e + n_r) {
        int r = gw - n_e;
        float4 v = xr[r * 32 + lane];
        float4 a = war4[lane];
        float d = v.x * a.x + v.y * a.y + v.z * a.z + v.w * a.w;
#pragma unroll
        for (int o = 16; o > 0; o >>= 1) d += __shfl_xor_sync(0xffffffffu, d, o);
        if (lane == 0) g_sr[r] = d;
    }
}

// ---------------- fused relation pipeline: x_r -> hid -> msg -> P (fp16, row-major) -----
#define RPB 8
__global__ __launch_bounds__(256) void k_rgemm(const float* __restrict__ xr,
                                               const float* __restrict__ W1, const float* __restrict__ b1,
                                               const float* __restrict__ W2, const float* __restrict__ b2,
                                               const float* __restrict__ Wr, int n_r) {
    __shared__ float sx[RPB * 128];
    __shared__ float shid[RPB * 256];
    __shared__ float smsg[RPB * 128];
    __shared__ float wt[32 * 256];
    int r0 = blockIdx.x * RPB;
    int tid = threadIdx.x;

    for (int i = tid; i < RPB * 128; i += 256) {
        int rr = i >> 7, k = i & 127, r = r0 + rr;
        sx[i] = (r < n_r) ? xr[r * 128 + k] : 0.f;
    }

    // ---- hid = x @ W1 + b1 ----
    {
        int j = tid;
        float acc[RPB];
        float bj = b1[j];
#pragma unroll
        for (int u = 0; u < RPB; u++) acc[u] = bj;
        for (int k0 = 0; k0 < 128; k0 += 32) {
            __syncthreads();
            for (int i = tid; i < 8192; i += 256)
                wt[i] = W1[(k0 + (i >> 8)) * 256 + (i & 255)];
            __syncthreads();
#pragma unroll 8
            for (int kk = 0; kk < 32; kk++) {
                float w = wt[kk * 256 + j];
#pragma unroll
                for (int u = 0; u < RPB; u++) acc[u] += sx[u * 128 + k0 + kk] * w;
            }
        }
#pragma unroll
        for (int u = 0; u < RPB; u++) shid[u * 256 + j] = acc[u];
    }
    __syncthreads();

    // ---- msg = x + hid @ W2 + b2 ----
    {
        int j = tid & 127, half = tid >> 7;
        float acc[RPB];
#pragma unroll
        for (int u = 0; u < RPB; u++) acc[u] = 0.f;
        for (int t = 0; t < 4; t++) {
            __syncthreads();
            for (int i = tid; i < 8192; i += 256) {
                int hh = i >> 12, loc = i & 4095, row = loc >> 7, col = loc & 127;
                wt[i] = W2[(hh * 128 + t * 32 + row) * 128 + col];
            }
            __syncthreads();
            const float* w = wt + half * 4096;
            int kbase = half * 128 + t * 32;
#pragma unroll 8
            for (int kk = 0; kk < 32; kk++) {
                float wv = w[kk * 128 + j];
#pragma unroll
                for (int u = 0; u < RPB; u++) acc[u] += shid[u * 256 + kbase + kk] * wv;
            }
        }
        __syncthreads();
        float* red = wt;
#pragma unroll
        for (int u = 0; u < RPB; u++) red[u * 256 + half * 128 + j] = acc[u];
        __syncthreads();
        if (half == 0) {
            float bj = b2[j];
#pragma unroll
            for (int u = 0; u < RPB; u++)
                smsg[u * 128 + j] = sx[u * 128 + j] + bj + red[u * 256 + j] + red[u * 256 + 128 + j];
        }
    }
    __syncthreads();

    // ---- P_side[r][j] = (msg @ Wr_side)[r][j], fp16 row-major ----
    {
        int j = tid;
        for (int side = 0; side < 2; side++) {
            float acc[RPB];
#pragma unroll
            for (int u = 0; u < RPB; u++) acc[u] = 0.f;
            for (int k0 = 0; k0 < 128; k0 += 32) {
                __syncthreads();
                for (int i = tid; i < 8192; i += 256)
                    wt[i] = Wr[(side * 128 + k0 + (i >> 8)) * 256 + (i & 255)];
                __syncthreads();
#pragma unroll 8
                for (int kk = 0; kk < 32; kk++) {
                    float w = wt[kk * 256 + j];
#pragma unroll
                    for (int u = 0; u < RPB; u++) acc[u] += smsg[u * 128 + k0 + kk] * w;
                }
            }
#pragma unroll
            for (int u = 0; u < RPB; u++) {
                int r = r0 + u;
                if (r < n_r) g_P16[((size_t)side * n_r + r) * 256 + j] = __float2half_rn(acc[u]);
            }
        }
    }
}

// ---------------- histogram (int4 vectorized, 4 edges/thread) ----------------
__global__ void k_hist(const int* __restrict__ h, const int* __restrict__ t, int E) {
    int i = blockIdx.x * blockDim.x + threadIdx.x;
    int e = i * 4;
    if (e + 3 < E) {
        int4 hv = *(const int4*)(h + e);
        int4 tv = *(const int4*)(t + e);
        atomicAdd(&g_cnt_h[hv.x], 1); atomicAdd(&g_cnt_h[hv.y], 1);
        atomicAdd(&g_cnt_h[hv.z], 1); atomicAdd(&g_cnt_h[hv.w], 1);
        atomicAdd(&g_cnt_t[tv.x], 1); atomicAdd(&g_cnt_t[tv.y], 1);
        atomicAdd(&g_cnt_t[tv.z], 1); atomicAdd(&g_cnt_t[tv.w], 1);
    } else {
        for (int k = e; k < E; k++) {
            atomicAdd(&g_cnt_h[h[k]], 1);
            atomicAdd(&g_cnt_t[t[k]], 1);
        }
    }
}

// ---------------- scan over PADDED counts (pad to multiple of 4 edges) ----------------
__global__ void k_scan1(int n_e) {
    __shared__ int s[1024];
    int y = blockIdx.y;
    const int* cnt = y ? g_cnt_t : g_cnt_h;
    int* st = y ? g_starts_t : g_starts_h;
    int i = blockIdx.x * 1024 + threadIdx.x;
    int v = (i < n_e) ? ((cnt[i] + 3) & ~3) : 0;
    s[threadIdx.x] = v;
    __syncthreads();
    for (int o = 1; o < 1024; o <<= 1) {
        int tv = (threadIdx.x >= (unsigned)o) ? s[threadIdx.x - o] : 0;
        __syncthreads();
        s[threadIdx.x] += tv;
        __syncthreads();
    }
    if (i < n_e) st[i] = s[threadIdx.x];
    if (threadIdx.x == 1023) g_bsum[y][blockIdx.x] = s[1023];
}

// parallel scan of block sums (nb <= 128)
__global__ void k_scan2(int nb) {
    __shared__ int s[128];
    int y = blockIdx.x;
    int tid = threadIdx.x;
    int v = (tid < nb) ? g_bsum[y][tid] : 0;
    s[tid] = v;
    __syncthreads();
    for (int o = 1; o < 128; o <<= 1) {
        int t = (tid >= o) ? s[tid - o] : 0;
        __syncthreads();
        s[tid] += t;
        __syncthreads();
    }
    if (tid < nb) g_bsum[y][tid] = s[tid] - v;   // exclusive
    if (tid == nb - 1) g_bsum[y][nb] = s[tid];   // total
}

__global__ void k_scan3(int n_e, int nb) {
    int y = blockIdx.y;
    const int* cnt = y ? g_cnt_t : g_cnt_h;
    int* st = y ? g_starts_t : g_starts_h;
    int* cur = y ? g_cur_t : g_cur_h;
    int i = blockIdx.x * 1024 + threadIdx.x;
    if (i < n_e) {
        int pc = (cnt[i] + 3) & ~3;
        int ex = st[i] - pc + g_bsum[y][blockIdx.x];
        st[i] = ex;
        cur[i] = ex;
    }
    if (i == 0) st[n_e] = g_bsum[y][nb];
}

// ---------------- place edges (off = BYTE offset r*512), 2 edges/thread ----------------
__global__ void k_place(const int* __restrict__ h, const int* __restrict__ t,
                        const int* __restrict__ rel, int E) {
    int i = blockIdx.x * blockDim.x + threadIdx.x;
    int e = i * 2;
    if (e >= E) return;
    int ne = min(2, E - e);
#pragma unroll
    for (int u = 0; u < 2; u++) {
        if (u < ne) {
            int hn = h[e + u], tn = t[e + u], r = rel[e + u];
            float sr = g_sr[r];
            float lh = g_sh[hn] + sr; lh = (lh > 0.f) ? lh : 0.01f * lh;
            float lt = g_st[tn] + sr; lt = (lt > 0.f) ? lt : 0.01f * lt;
            float zh = __expf(lh), zt = __expf(lt);
            float ro = __int_as_float(r * 512);
            int ph = atomicAdd(&g_cur_h[hn], 1);
            g_pack_h[ph] = make_float2(zh, ro);
            int pt = atomicAdd(&g_cur_t[tn], 1);
            g_pack_t[pt] = make_float2(zt, ro);
        }
    }
}

// ---------------- main SpMM: SINGLE PASS (R11 structure) + L1 residency hints ----------
// Warp per node; per edge one coalesced LDG.128/lane (evict_last) fetches the 512B P row;
// pack stream read with evict_first so it never displaces the hot P table in L1.
__global__ __launch_bounds__(256) void k_main(const float* __restrict__ br,
                                              float* __restrict__ out,
                                              int n_e, int n_r) {
    int gw = (blockIdx.x * blockDim.x + threadIdx.x) >> 5;
    int lane = threadIdx.x & 31;
    if (gw >= n_e) return;
    int n = gw;

    const char* Pb = (const char*)g_P16 + lane * 16;   // this lane's 16B of each row
    const char* Pt = Pb + (size_t)n_r * 512;

    float res[8];
    {
        float4 b0 = *(const float4*)(br + lane * 8);
        float4 b1 = *(const float4*)(br + lane * 8 + 4);
        res[0] = b0.x; res[1] = b0.y; res[2] = b0.z; res[3] = b0.w;
        res[4] = b1.x; res[5] = b1.y; res[6] = b1.z; res[7] = b1.w;
    }

    // ---- h side ----
    {
        int s0 = g_starts_h[n], s1 = g_starts_h[n + 1];
        float zs = 0.f;
        float acc[8];
#pragma unroll
        for (int k = 0; k < 8; k++) acc[k] = 0.f;
        const float2* __restrict__ pk = g_pack_h;
        for (int i = s0; i < s1; i += 4) {
#pragma unroll
            for (int u = 0; u < 4; u++) {
                int j = i + u;
                float2 p = (j < s1) ? ldg_pack_stream(pk + j) : make_float2(0.f, 0.f);
                uint4 rv = ldg_row_resident(Pb + __float_as_int(p.y));
                zs += p.x;
                float2 v0 = __half22float2(*(const __half2*)&rv.x);
                float2 v1 = __half22float2(*(const __half2*)&rv.y);
                float2 v2 = __half22float2(*(const __half2*)&rv.z);
                float2 v3 = __half22float2(*(const __half2*)&rv.w);
                acc[0] = fmaf(p.x, v0.x, acc[0]); acc[1] = fmaf(p.x, v0.y, acc[1]);
                acc[2] = fmaf(p.x, v1.x, acc[2]); acc[3] = fmaf(p.x, v1.y, acc[3]);
                acc[4] = fmaf(p.x, v2.x, acc[4]); acc[5] = fmaf(p.x, v2.y, acc[5]);
                acc[6] = fmaf(p.x, v3.x, acc[6]); acc[7] = fmaf(p.x, v3.y, acc[7]);
            }
        }
        float inv = 1.f / (zs + 1e-16f);
#pragma unroll
        for (int k = 0; k < 8; k++) res[k] = fmaf(acc[k], inv, res[k]);
    }

    // ---- t side ----
    {
        int s0 = g_starts_t[n], s1 = g_starts_t[n + 1];
        float zs = 0.f;
        float acc[8];
#pragma unroll
        for (int k = 0; k < 8; k++) acc[k] = 0.f;
        const float2* __restrict__ pk = g_pack_t;
        for (int i = s0; i < s1; i += 4) {
#pragma unroll
            for (int u = 0; u < 4; u++) {
                int j = i + u;
                float2 p = (j < s1) ? ldg_pack_stream(pk + j) : make_float2(0.f, 0.f);
                uint4 rv = ldg_row_resident(Pt + __float_as_int(p.y));
                zs += p.x;
                float2 v0 = __half22float2(*(const __half2*)&rv.x);
                float2 v1 = __half22float2(*(const __half2*)&rv.y);
                float2 v2 = __half22float2(*(const __half2*)&rv.z);
                float2 v3 = __half22float2(*(const __half2*)&rv.w);
                acc[0] = fmaf(p.x, v0.x, acc[0]); acc[1] = fmaf(p.x, v0.y, acc[1]);
                acc[2] = fmaf(p.x, v1.x, acc[2]); acc[3] = fmaf(p.x, v1.y, acc[3]);
                acc[4] = fmaf(p.x, v2.x, acc[4]); acc[5] = fmaf(p.x, v2.y, acc[5]);
                acc[6] = fmaf(p.x, v3.x, acc[6]); acc[7] = fmaf(p.x, v3.y, acc[7]);
            }
        }
        float inv = 1.f / (zs + 1e-16f);
#pragma unroll
        for (int k = 0; k < 8; k++) res[k] = fmaf(acc[k], inv, res[k]);
    }

    // ---- single coalesced store: 1 KB per warp ----
    float* o = out + (size_t)n * 256 + lane * 8;
    *(float4*)o = make_float4(res[0], res[1], res[2], res[3]);
    *(float4*)(o + 4) = make_float4(res[4], res[5], res[6], res[7]);
}

// ---------------- launch ----------------
extern "C" void kernel_launch(void* const* d_in, const int* in_sizes, int n_in,
                              void* d_out, int out_size) {
    const float* xe  = (const float*)d_in[0];
    const float* xr  = (const float*)d_in[1];
    const int*   ei  = (const int*)d_in[2];
    const int*   rel = (const int*)d_in[3];
    const float* wah = (const float*)d_in[5];
    const float* wat = (const float*)d_in[6];
    const float* war = (const float*)d_in[7];
    const float* W1  = (const float*)d_in[8];
    const float* b1  = (const float*)d_in[9];
    const float* W2  = (const float*)d_in[10];
    const float* b2  = (const float*)d_in[11];
    const float* Wr  = (const float*)d_in[12];
    const float* br  = (const float*)d_in[13];
    float* out = (float*)d_out;

    int n_e = in_sizes[0] / 128;
    int n_r = in_sizes[1] / 128;
    int E   = in_sizes[3];
    const int* h = ei;
    const int* t = ei + E;
    int nb = (n_e + 1023) / 1024;

    k_scores<<<((n_e + n_r) * 32 + 255) / 256, 256>>>((const float4*)xe, (const float4*)xr,
                                                      (const float4*)wah, (const float4*)wat,
                                                      (const float4*)war, n_e, n_r);
    k_rgemm<<<(n_r + RPB - 1) / RPB, 256>>>(xr, W1, b1, W2, b2, Wr, n_r);
    k_hist<<<(E / 4 + 256) / 256, 256>>>(h, t, E);
    k_scan1<<<dim3(nb, 2), 1024>>>(n_e);
    k_scan2<<<2, 128>>>(nb);
    k_scan3<<<dim3(nb, 2), 1024>>>(n_e, nb);
    k_place<<<(E / 2 + 256) / 256, 256>>>(h, t, rel, E);

    k_main<<<(n_e * 32 + 255) / 256, 256>>>(br, out, n_e, n_r);
}

// round 14
// speedup vs baseline: 1.1891x; 1.0630x over previous
#include <cuda_runtime.h>
#include <cuda_fp16.h>
#include <math.h>

#define MAX_NE 100000
#define MAX_NR 1000
#define MAX_E  1000000
#define PACK_CAP 1800064   // E + padding + guard

// ---------------- scratch ----------------
__device__ float  g_sh[MAX_NE];
__device__ float  g_st[MAX_NE];
__device__ float  g_sr[MAX_NR];
// fp16 P tables: [side(2)][rel][256]; 512B per row, L2-resident (1 MB total)
__device__ __half g_P16[2 * MAX_NR * 256];
__device__ int    g_cnt_h[MAX_NE];
__device__ int    g_cnt_t[MAX_NE];
__device__ int    g_starts_h[MAX_NE + 1];  // PADDED exclusive starts (multiples of 4 edges)
__device__ int    g_starts_t[MAX_NE + 1];
__device__ int    g_cur_h[MAX_NE];
__device__ int    g_cur_t[MAX_NE];
// pad slots are NEVER written: BSS-zero => {z=0, off=0} -> loads P row 0, FFMA x0 = inert.
__device__ float2 g_pack_h[PACK_CAP];
__device__ float2 g_pack_t[PACK_CAP];
__device__ int    g_bsum[2][160];

// P-row load: keep resident in L1 (hot 1MB table, re-read 2M times)
__device__ __forceinline__ uint4 ldg_row_resident(const void* p) {
    uint4 v;
    asm("ld.global.nc.L1::evict_last.v4.u32 {%0,%1,%2,%3}, [%4];"
        : "=r"(v.x), "=r"(v.y), "=r"(v.z), "=r"(v.w) : "l"(p));
    return v;
}
// pack load: streaming, read exactly once -> don't pollute L1
__device__ __forceinline__ float2 ldg_pack_stream(const float2* p) {
    float2 v;
    asm("ld.global.nc.L1::evict_first.v2.f32 {%0,%1}, [%2];"
        : "=f"(v.x), "=f"(v.y) : "l"(p));
    return v;
}

// ---------------- prep1: fused edge histogram (blocks [0,nbh)) + attention scores ------
__global__ void k_prep1(const float4* __restrict__ xe, const float4* __restrict__ xr,
                        const float4* __restrict__ wah4, const float4* __restrict__ wat4,
                        const float4* __restrict__ war4,
                        const int* __restrict__ h, const int* __restrict__ t,
                        int n_e, int n_r, int E, int nbh) {
    if (blockIdx.x < (unsigned)nbh) {
        // ---- histogram role (int4 vectorized, 4 edges/thread) ----
        int i = blockIdx.x * blockDim.x + threadIdx.x;
        int e = i * 4;
        if (e + 3 < E) {
            int4 hv = *(const int4*)(h + e);
            int4 tv = *(const int4*)(t + e);
            atomicAdd(&g_cnt_h[hv.x], 1); atomicAdd(&g_cnt_h[hv.y], 1);
            atomicAdd(&g_cnt_h[hv.z], 1); atomicAdd(&g_cnt_h[hv.w], 1);
            atomicAdd(&g_cnt_t[tv.x], 1); atomicAdd(&g_cnt_t[tv.y], 1);
            atomicAdd(&g_cnt_t[tv.z], 1); atomicAdd(&g_cnt_t[tv.w], 1);
        } else if (e < E) {
            for (int k = e; k < E; k++) {
                atomicAdd(&g_cnt_h[h[k]], 1);
                atomicAdd(&g_cnt_t[t[k]], 1);
            }
        }
        return;
    }
    // ---- scores role ----
    int gw = ((blockIdx.x - nbh) * blockDim.x + threadIdx.x) >> 5;
    int lane = threadIdx.x & 31;
    if (gw < n_e) {
        float4 v = xe[(size_t)gw * 32 + lane];
        float4 a = wah4[lane];
        float4 b = wat4[lane];
        float da = v.x * a.x + v.y * a.y + v.z * a.z + v.w * a.w;
        float db = v.x * b.x + v.y * b.y + v.z * b.z + v.w * b.w;
#pragma unroll
        for (int o = 16; o > 0; o >>= 1) {
            da += __shfl_xor_sync(0xffffffffu, da, o);
            db += __shfl_xor_sync(0xffffffffu, db, o);
        }
        if (lane == 0) { g_sh[gw] = da; g_st[gw] = db; }
    } else if (gw < n_e + n_r) {
        int r = gw - n_e;
        float4 v = xr[r * 32 + lane];
        float4 a = war4[lane];
        float d = v.x * a.x + v.y * a.y + v.z * a.z + v.w * a.w;
#pragma unroll
        for (int o = 16; o > 0; o >>= 1) d += __shfl_xor_sync(0xffffffffu, d, o);
        if (lane == 0) g_sr[r] = d;
    }
}

// zero counters (separate tiny kernel so hist can't race the zeroing)
__global__ void k_zero(int n_e) {
    int i = blockIdx.x * blockDim.x + threadIdx.x;
    if (i < n_e) { g_cnt_h[i] = 0; g_cnt_t[i] = 0; }
}

// ---------------- scan over PADDED counts (pad to multiple of 4 edges) ----------------
__global__ void k_scan1(int n_e) {
    __shared__ int s[1024];
    int y = blockIdx.y;
    const int* cnt = y ? g_cnt_t : g_cnt_h;
    int* st = y ? g_starts_t : g_starts_h;
    int i = blockIdx.x * 1024 + threadIdx.x;
    int v = (i < n_e) ? ((cnt[i] + 3) & ~3) : 0;
    s[threadIdx.x] = v;
    __syncthreads();
    for (int o = 1; o < 1024; o <<= 1) {
        int tv = (threadIdx.x >= (unsigned)o) ? s[threadIdx.x - o] : 0;
        __syncthreads();
        s[threadIdx.x] += tv;
        __syncthreads();
    }
    if (i < n_e) st[i] = s[threadIdx.x];
    if (threadIdx.x == 1023) g_bsum[y][blockIdx.x] = s[1023];
}

__global__ void k_scan2(int nb) {
    __shared__ int s[128];
    int y = blockIdx.x;
    int tid = threadIdx.x;
    int v = (tid < nb) ? g_bsum[y][tid] : 0;
    s[tid] = v;
    __syncthreads();
    for (int o = 1; o < 128; o <<= 1) {
        int t = (tid >= o) ? s[tid - o] : 0;
        __syncthreads();
        s[tid] += t;
        __syncthreads();
    }
    if (tid < nb) g_bsum[y][tid] = s[tid] - v;   // exclusive
    if (tid == nb - 1) g_bsum[y][nb] = s[tid];   // total
}

__global__ void k_scan3(int n_e, int nb) {
    int y = blockIdx.y;
    const int* cnt = y ? g_cnt_t : g_cnt_h;
    int* st = y ? g_starts_t : g_starts_h;
    int* cur = y ? g_cur_t : g_cur_h;
    int i = blockIdx.x * 1024 + threadIdx.x;
    if (i < n_e) {
        int pc = (cnt[i] + 3) & ~3;
        int ex = st[i] - pc + g_bsum[y][blockIdx.x];
        st[i] = ex;
        cur[i] = ex;
    }
    if (i == 0) st[n_e] = g_bsum[y][nb];
}

// ---------------- prep2: fused relation pipeline (blocks [0,125)) + edge placement -----
#define RPB 8
__global__ __launch_bounds__(256) void k_prep2(const float* __restrict__ xr,
                                               const float* __restrict__ W1, const float* __restrict__ b1,
                                               const float* __restrict__ W2, const float* __restrict__ b2,
                                               const float* __restrict__ Wr,
                                               const int* __restrict__ h, const int* __restrict__ t,
                                               const int* __restrict__ rel,
                                               int n_r, int E, int nbr) {
    __shared__ float sx[RPB * 128];     // 4 KB
    __shared__ float shid[RPB * 256];   // 8 KB
    __shared__ float smsg[RPB * 128];   // 4 KB
    __shared__ float wt[32 * 256];      // 32 KB
    int tid = threadIdx.x;

    if (blockIdx.x >= (unsigned)nbr) {
        // ---- place role: 2 edges/thread ----
        int i = (blockIdx.x - nbr) * blockDim.x + tid;
        int e = i * 2;
        if (e >= E) return;
        int ne = min(2, E - e);
#pragma unroll
        for (int u = 0; u < 2; u++) {
            if (u < ne) {
                int hn = h[e + u], tn = t[e + u], r = rel[e + u];
                float sr = g_sr[r];
                float lh = g_sh[hn] + sr; lh = (lh > 0.f) ? lh : 0.01f * lh;
                float lt = g_st[tn] + sr; lt = (lt > 0.f) ? lt : 0.01f * lt;
                float zh = __expf(lh), zt = __expf(lt);
                float ro = __int_as_float(r * 512);
                int ph = atomicAdd(&g_cur_h[hn], 1);
                g_pack_h[ph] = make_float2(zh, ro);
                int pt = atomicAdd(&g_cur_t[tn], 1);
                g_pack_t[pt] = make_float2(zt, ro);
            }
        }
        return;
    }

    // ---- rgemm role ----
    int r0 = blockIdx.x * RPB;

    for (int i = tid; i < RPB * 128; i += 256) {
        int rr = i >> 7, k = i & 127, r = r0 + rr;
        sx[i] = (r < n_r) ? xr[r * 128 + k] : 0.f;
    }

    // ---- hid = x @ W1 + b1 ----
    {
        int j = tid;
        float acc[RPB];
        float bj = b1[j];
#pragma unroll
        for (int u = 0; u < RPB; u++) acc[u] = bj;
        for (int k0 = 0; k0 < 128; k0 += 32) {
            __syncthreads();
            for (int i = tid; i < 8192; i += 256)
                wt[i] = W1[(k0 + (i >> 8)) * 256 + (i & 255)];
            __syncthreads();
#pragma unroll 8
            for (int kk = 0; kk < 32; kk++) {
                float w = wt[kk * 256 + j];
#pragma unroll
                for (int u = 0; u < RPB; u++) acc[u] += sx[u * 128 + k0 + kk] * w;
            }
        }
#pragma unroll
        for (int u = 0; u < RPB; u++) shid[u * 256 + j] = acc[u];
    }
    __syncthreads();

    // ---- msg = x + hid @ W2 + b2 ----
    {
        int j = tid & 127, half = tid >> 7;
        float acc[RPB];
#pragma unroll
        for (int u = 0; u < RPB; u++) acc[u] = 0.f;
        for (int tt = 0; tt < 4; tt++) {
            __syncthreads();
            for (int i = tid; i < 8192; i += 256) {
                int hh = i >> 12, loc = i & 4095, row = loc >> 7, col = loc & 127;
                wt[i] = W2[(hh * 128 + tt * 32 + row) * 128 + col];
            }
            __syncthreads();
            const float* w = wt + half * 4096;
            int kbase = half * 128 + tt * 32;
#pragma unroll 8
            for (int kk = 0; kk < 32; kk++) {
                float wv = w[kk * 128 + j];
#pragma unroll
                for (int u = 0; u < RPB; u++) acc[u] += shid[u * 256 + kbase + kk] * wv;
            }
        }
        __syncthreads();
        float* red = wt;
#pragma unroll
        for (int u = 0; u < RPB; u++) red[u * 256 + half * 128 + j] = acc[u];
        __syncthreads();
        if (half == 0) {
            float bj = b2[j];
#pragma unroll
            for (int u = 0; u < RPB; u++)
                smsg[u * 128 + j] = sx[u * 128 + j] + bj + red[u * 256 + j] + red[u * 256 + 128 + j];
        }
    }
    __syncthreads();

    // ---- P_side[r][j] = (msg @ Wr_side)[r][j], fp16 row-major ----
    {
        int j = tid;
        for (int side = 0; side < 2; side++) {
            float acc[RPB];
#pragma unroll
            for (int u = 0; u < RPB; u++) acc[u] = 0.f;
            for (int k0 = 0; k0 < 128; k0 += 32) {
                __syncthreads();
                for (int i = tid; i < 8192; i += 256)
                    wt[i] = Wr[(side * 128 + k0 + (i >> 8)) * 256 + (i & 255)];
                __syncthreads();
#pragma unroll 8
                for (int kk = 0; kk < 32; kk++) {
                    float w = wt[kk * 256 + j];
#pragma unroll
                    for (int u = 0; u < RPB; u++) acc[u] += smsg[u * 128 + k0 + kk] * w;
                }
            }
#pragma unroll
            for (int u = 0; u < RPB; u++) {
                int r = r0 + u;
                if (r < n_r) g_P16[((size_t)side * n_r + r) * 256 + j] = __float2half_rn(acc[u]);
            }
        }
    }
}

// ---------------- main SpMM: SINGLE PASS (R11 structure) + L1 residency hints ----------
__global__ __launch_bounds__(256) void k_main(const float* __restrict__ br,
                                              float* __restrict__ out,
                                              int n_e, int n_r) {
    int gw = (blockIdx.x * blockDim.x + threadIdx.x) >> 5;
    int lane = threadIdx.x & 31;
    if (gw >= n_e) return;
    int n = gw;

    const char* Pb = (const char*)g_P16 + lane * 16;   // this lane's 16B of each row
    const char* Pt = Pb + (size_t)n_r * 512;

    float res[8];
    {
        float4 b0 = *(const float4*)(br + lane * 8);
        float4 b1 = *(const float4*)(br + lane * 8 + 4);
        res[0] = b0.x; res[1] = b0.y; res[2] = b0.z; res[3] = b0.w;
        res[4] = b1.x; res[5] = b1.y; res[6] = b1.z; res[7] = b1.w;
    }

    // ---- h side ----
    {
        int s0 = g_starts_h[n], s1 = g_starts_h[n + 1];
        float zs = 0.f;
        float acc[8];
#pragma unroll
        for (int k = 0; k < 8; k++) acc[k] = 0.f;
        const float2* __restrict__ pk = g_pack_h;
        for (int i = s0; i < s1; i += 4) {
#pragma unroll
            for (int u = 0; u < 4; u++) {
                int j = i + u;
                float2 p = (j < s1) ? ldg_pack_stream(pk + j) : make_float2(0.f, 0.f);
                uint4 rv = ldg_row_resident(Pb + __float_as_int(p.y));
                zs += p.x;
                float2 v0 = __half22float2(*(const __half2*)&rv.x);
                float2 v1 = __half22float2(*(const __half2*)&rv.y);
                float2 v2 = __half22float2(*(const __half2*)&rv.z);
                float2 v3 = __half22float2(*(const __half2*)&rv.w);
                acc[0] = fmaf(p.x, v0.x, acc[0]); acc[1] = fmaf(p.x, v0.y, acc[1]);
                acc[2] = fmaf(p.x, v1.x, acc[2]); acc[3] = fmaf(p.x, v1.y, acc[3]);
                acc[4] = fmaf(p.x, v2.x, acc[4]); acc[5] = fmaf(p.x, v2.y, acc[5]);
                acc[6] = fmaf(p.x, v3.x, acc[6]); acc[7] = fmaf(p.x, v3.y, acc[7]);
            }
        }
        float inv = 1.f / (zs + 1e-16f);
#pragma unroll
        for (int k = 0; k < 8; k++) res[k] = fmaf(acc[k], inv, res[k]);
    }

    // ---- t side ----
    {
        int s0 = g_starts_t[n], s1 = g_starts_t[n + 1];
        float zs = 0.f;
        float acc[8];
#pragma unroll
        for (int k = 0; k < 8; k++) acc[k] = 0.f;
        const float2* __restrict__ pk = g_pack_t;
        for (int i = s0; i < s1; i += 4) {
#pragma unroll
            for (int u = 0; u < 4; u++) {
                int j = i + u;
                float2 p = (j < s1) ? ldg_pack_stream(pk + j) : make_float2(0.f, 0.f);
                uint4 rv = ldg_row_resident(Pt + __float_as_int(p.y));
                zs += p.x;
                float2 v0 = __half22float2(*(const __half2*)&rv.x);
                float2 v1 = __half22float2(*(const __half2*)&rv.y);
                float2 v2 = __half22float2(*(const __half2*)&rv.z);
                float2 v3 = __half22float2(*(const __half2*)&rv.w);
                acc[0] = fmaf(p.x, v0.x, acc[0]); acc[1] = fmaf(p.x, v0.y, acc[1]);
                acc[2] = fmaf(p.x, v1.x, acc[2]); acc[3] = fmaf(p.x, v1.y, acc[3]);
                acc[4] = fmaf(p.x, v2.x, acc[4]); acc[5] = fmaf(p.x, v2.y, acc[5]);
                acc[6] = fmaf(p.x, v3.x, acc[6]); acc[7] = fmaf(p.x, v3.y, acc[7]);
            }
        }
        float inv = 1.f / (zs + 1e-16f);
#pragma unroll
        for (int k = 0; k < 8; k++) res[k] = fmaf(acc[k], inv, res[k]);
    }

    // ---- single coalesced store: 1 KB per warp ----
    float* o = out + (size_t)n * 256 + lane * 8;
    *(float4*)o = make_float4(res[0], res[1], res[2], res[3]);
    *(float4*)(o + 4) = make_float4(res[4], res[5], res[6], res[7]);
}

// ---------------- launch ----------------
extern "C" void kernel_launch(void* const* d_in, const int* in_sizes, int n_in,
                              void* d_out, int out_size) {
    const float* xe  = (const float*)d_in[0];
    const float* xr  = (const float*)d_in[1];
    const int*   ei  = (const int*)d_in[2];
    const int*   rel = (const int*)d_in[3];
    const float* wah = (const float*)d_in[5];
    const float* wat = (const float*)d_in[6];
    const float* war = (const float*)d_in[7];
    const float* W1  = (const float*)d_in[8];
    const float* b1  = (const float*)d_in[9];
    const float* W2  = (const float*)d_in[10];
    const float* b2  = (const float*)d_in[11];
    const float* Wr  = (const float*)d_in[12];
    const float* br  = (const float*)d_in[13];
    float* out = (float*)d_out;

    int n_e = in_sizes[0] / 128;
    int n_r = in_sizes[1] / 128;
    int E   = in_sizes[3];
    const int* h = ei;
    const int* t = ei + E;
    int nb = (n_e + 1023) / 1024;

    int nbh = (E / 4 + 256) / 256;                       // hist blocks
    int nbs = ((n_e + n_r) * 32 + 255) / 256;            // scores blocks
    int nbr = (n_r + RPB - 1) / RPB;                     // rgemm blocks
    int nbp = (E / 2 + 255) / 256;                       // place blocks

    k_zero<<<(n_e + 255) / 256, 256>>>(n_e);
    k_prep1<<<nbh + nbs, 256>>>((const float4*)xe, (const float4*)xr,
                                (const float4*)wah, (const float4*)wat, (const float4*)war,
                                h, t, n_e, n_r, E, nbh);
    k_scan1<<<dim3(nb, 2), 1024>>>(n_e);
    k_scan2<<<2, 128>>>(nb);
    k_scan3<<<dim3(nb, 2), 1024>>>(n_e, nb);
    k_prep2<<<nbr + nbp, 256>>>(xr, W1, b1, W2, b2, Wr, h, t, rel, n_r, E, nbr);

    k_main<<<(n_e * 32 + 255) / 256, 256>>>(br, out, n_e, n_r);
}